// round 7
// baseline (speedup 1.0000x reference)
#include <cuda_runtime.h>
#include <cuda_bf16.h>
#include <cstdint>
#include <math.h>

// ---------------- problem constants ----------------
constexpr int T = 16384;   // tokens
constexpr int H = 2048;    // hidden
constexpr int E = 128;     // experts
constexpr int TOPK = 8;

// ---------------- GEMM config ----------------
constexpr int BM = 128;               // tokens per CTA
constexpr int CHUNK = 32;             // fp32 k per pipeline chunk
constexpr int NCHUNK = H / CHUNK;     // 64
constexpr int TSTRIDE = 80;           // bytes per tile row: 64B data + 16B pad (conflict-free ldmatrix)
constexpr int TILE_B = 128 * TSTRIDE; // 10240 B per component tile
constexpr int STAGE_B = 6 * TILE_B;   // A1,A2,A3,B1,B2,B3 = 61440
constexpr int SMEM_TOTAL = 2 * STAGE_B;  // 122880

// pre-split W components (bf16 triple-split of fp32), [E][H]
__device__ __align__(16) __nv_bfloat16 g_w1[E * H];
__device__ __align__(16) __nv_bfloat16 g_w2[E * H];
__device__ __align__(16) __nv_bfloat16 g_w3[E * H];

// ---------------- helpers ----------------
__device__ __forceinline__ uint32_t smem_u32(const void* p) {
    uint32_t a;
    asm("{ .reg .u64 t; cvta.to.shared.u64 t, %1; cvt.u32.u64 %0, t; }" : "=r"(a) : "l"(p));
    return a;
}
__device__ __forceinline__ void ldsm4(uint32_t* r, uint32_t addr) {
    asm volatile("ldmatrix.sync.aligned.m8n8.x4.shared.b16 {%0,%1,%2,%3}, [%4];"
                 : "=r"(r[0]), "=r"(r[1]), "=r"(r[2]), "=r"(r[3]) : "r"(addr));
}
__device__ __forceinline__ void mma16816(float* c, const uint32_t* a, const uint32_t* b) {
    asm volatile(
        "mma.sync.aligned.m16n8k16.row.col.f32.bf16.bf16.f32 "
        "{%0,%1,%2,%3}, {%4,%5,%6,%7}, {%8,%9}, {%0,%1,%2,%3};"
        : "+f"(c[0]), "+f"(c[1]), "+f"(c[2]), "+f"(c[3])
        : "r"(a[0]), "r"(a[1]), "r"(a[2]), "r"(a[3]), "r"(b[0]), "r"(b[1]));
}

// ---------------- W triple-split precompute ----------------
__global__ __launch_bounds__(256) void split_w_kernel(const float* __restrict__ W) {
    int i = blockIdx.x * blockDim.x + threadIdx.x;   // one float4 per thread
    float4 v = reinterpret_cast<const float4*>(W)[i];
    __nv_bfloat162 a0 = __floats2bfloat162_rn(v.x, v.y);
    __nv_bfloat162 a1 = __floats2bfloat162_rn(v.z, v.w);
    float r0 = v.x - __low2float(a0), r1 = v.y - __high2float(a0);
    float r2 = v.z - __low2float(a1), r3 = v.w - __high2float(a1);
    __nv_bfloat162 b0 = __floats2bfloat162_rn(r0, r1);
    __nv_bfloat162 b1 = __floats2bfloat162_rn(r2, r3);
    r0 -= __low2float(b0); r1 -= __high2float(b0);
    r2 -= __low2float(b1); r3 -= __high2float(b1);
    __nv_bfloat162 c0 = __floats2bfloat162_rn(r0, r1);
    __nv_bfloat162 c1 = __floats2bfloat162_rn(r2, r3);
    reinterpret_cast<__nv_bfloat162*>(g_w1)[2 * i] = a0;
    reinterpret_cast<__nv_bfloat162*>(g_w1)[2 * i + 1] = a1;
    reinterpret_cast<__nv_bfloat162*>(g_w2)[2 * i] = b0;
    reinterpret_cast<__nv_bfloat162*>(g_w2)[2 * i + 1] = b1;
    reinterpret_cast<__nv_bfloat162*>(g_w3)[2 * i] = c0;
    reinterpret_cast<__nv_bfloat162*>(g_w3)[2 * i + 1] = c1;
}

// ---------------- bf16x6 HMMA router GEMM, pipelined staging ----------------
// C[t][e] = X[t][:] . W[e][:], fp32-equivalent via 3-way bf16 splits (6 terms).
__global__ __launch_bounds__(256, 1) void router_gemm_mma(const float* __restrict__ X,
                                                          float* __restrict__ Cout) {
    extern __shared__ char smem[];
    const int tid = threadIdx.x;
    const int wid = tid >> 5;
    const int lane = tid & 31;
    const int m0 = blockIdx.x * BM;

    // gmem load mapping: 2 threads per row, 16 floats (64B) each
    const int lrow = tid >> 1;          // 0..127
    const int lhalf = tid & 1;          // 0/1
    const float* Xbase = X + (size_t)(m0 + lrow) * H + lhalf * 16;
    const __nv_bfloat16* Wb1 = g_w1 + (size_t)lrow * H + lhalf * 16;
    const __nv_bfloat16* Wb2 = g_w2 + (size_t)lrow * H + lhalf * 16;
    const __nv_bfloat16* Wb3 = g_w3 + (size_t)lrow * H + lhalf * 16;
    const uint32_t rb = (uint32_t)lrow * TSTRIDE + lhalf * 32;  // smem tile byte base

    // warp tile: 2 warps in M (64 rows), 4 warps in N (32 cols)
    const int wm = (wid >> 2) * 64;
    const int wn = (wid & 3) * 32;

    float acc[4][4][4];
#pragma unroll
    for (int mt = 0; mt < 4; mt++)
#pragma unroll
        for (int nt = 0; nt < 4; nt++)
#pragma unroll
            for (int j = 0; j < 4; j++) acc[mt][nt][j] = 0.0f;

    float4 xv[4];
    uint4 wv[3][2];

    const uint32_t sbase = smem_u32(smem);

    // store regs -> stage buffer `buf` (split X into 3 bf16 comps; copy W comps)
    auto store_stage = [&](int buf) {
        char* stage = smem + buf * STAGE_B;
        char* A1 = stage;
        char* A2 = stage + TILE_B;
        char* A3 = stage + 2 * TILE_B;
#pragma unroll
        for (int q = 0; q < 4; q++) {
            float4 v = xv[q];
            uint32_t off = rb + q * 8;
            __nv_bfloat162 p1a = __floats2bfloat162_rn(v.x, v.y);
            __nv_bfloat162 p1b = __floats2bfloat162_rn(v.z, v.w);
            *reinterpret_cast<uint2*>(A1 + off) =
                make_uint2(*reinterpret_cast<uint32_t*>(&p1a), *reinterpret_cast<uint32_t*>(&p1b));
            float r0 = v.x - __low2float(p1a);
            float r1 = v.y - __high2float(p1a);
            float r2 = v.z - __low2float(p1b);
            float r3 = v.w - __high2float(p1b);
            __nv_bfloat162 p2a = __floats2bfloat162_rn(r0, r1);
            __nv_bfloat162 p2b = __floats2bfloat162_rn(r2, r3);
            *reinterpret_cast<uint2*>(A2 + off) =
                make_uint2(*reinterpret_cast<uint32_t*>(&p2a), *reinterpret_cast<uint32_t*>(&p2b));
            r0 -= __low2float(p2a); r1 -= __high2float(p2a);
            r2 -= __low2float(p2b); r3 -= __high2float(p2b);
            __nv_bfloat162 p3a = __floats2bfloat162_rn(r0, r1);
            __nv_bfloat162 p3b = __floats2bfloat162_rn(r2, r3);
            *reinterpret_cast<uint2*>(A3 + off) =
                make_uint2(*reinterpret_cast<uint32_t*>(&p3a), *reinterpret_cast<uint32_t*>(&p3b));
        }
#pragma unroll
        for (int comp = 0; comp < 3; comp++) {
            char* Bt = stage + (3 + comp) * TILE_B;
            *reinterpret_cast<uint4*>(Bt + rb) = wv[comp][0];
            *reinterpret_cast<uint4*>(Bt + rb + 16) = wv[comp][1];
        }
    };

    // prologue: load + stage chunk 0 into buffer 0
    {
#pragma unroll
        for (int q = 0; q < 4; q++) xv[q] = *reinterpret_cast<const float4*>(Xbase + q * 4);
        wv[0][0] = *reinterpret_cast<const uint4*>(Wb1);
        wv[0][1] = *reinterpret_cast<const uint4*>(Wb1 + 8);
        wv[1][0] = *reinterpret_cast<const uint4*>(Wb2);
        wv[1][1] = *reinterpret_cast<const uint4*>(Wb2 + 8);
        wv[2][0] = *reinterpret_cast<const uint4*>(Wb3);
        wv[2][1] = *reinterpret_cast<const uint4*>(Wb3 + 8);
        store_stage(0);
    }
    __syncthreads();

#pragma unroll 1
    for (int c = 0; c < NCHUNK; c++) {
        const int cur = c & 1;
        const bool more = (c + 1 < NCHUNK);

        // ---- (1) issue prefetch LDGs for chunk c+1 (consumed by stores after MMAs) ----
        if (more) {
            const float* xp = Xbase + (c + 1) * CHUNK;
#pragma unroll
            for (int q = 0; q < 4; q++) xv[q] = *reinterpret_cast<const float4*>(xp + q * 4);
            const int wo = (c + 1) * CHUNK;
            wv[0][0] = *reinterpret_cast<const uint4*>(Wb1 + wo);
            wv[0][1] = *reinterpret_cast<const uint4*>(Wb1 + wo + 8);
            wv[1][0] = *reinterpret_cast<const uint4*>(Wb2 + wo);
            wv[1][1] = *reinterpret_cast<const uint4*>(Wb2 + wo + 8);
            wv[2][0] = *reinterpret_cast<const uint4*>(Wb3 + wo);
            wv[2][1] = *reinterpret_cast<const uint4*>(Wb3 + wo + 8);
        }

        // ---- (2) compute on stage cur ----
        const uint32_t st = sbase + cur * STAGE_B;
#pragma unroll
        for (int ks = 0; ks < 2; ks++) {
            // B fragments: 3 comps x 4 n-tiles (2 ldmatrix.x4 per comp)
            uint32_t bq[3][8];
            {
                const uint32_t nrow = wn + (lane & 7) + ((lane >> 4) & 1) * 8;
                const uint32_t koff = ks * 32 + ((lane >> 3) & 1) * 16;
#pragma unroll
                for (int comp = 0; comp < 3; comp++) {
                    uint32_t basea = st + (3 + comp) * TILE_B + nrow * TSTRIDE + koff;
                    ldsm4(&bq[comp][0], basea);                  // n-tiles 0,1
                    ldsm4(&bq[comp][4], basea + 16 * TSTRIDE);   // n-tiles 2,3
                }
            }
            // A comps on demand; terms (ca,cb) with ca+cb <= 2
            const uint32_t arow = wm + (lane & 15);
            const uint32_t akoff = ks * 32 + (lane >> 4) * 16;
#pragma unroll
            for (int ca = 0; ca < 3; ca++) {
                uint32_t abase = st + ca * TILE_B + arow * TSTRIDE + akoff;
                uint32_t aq[4][4];
#pragma unroll
                for (int mt = 0; mt < 4; mt++) ldsm4(aq[mt], abase + mt * 16 * TSTRIDE);
#pragma unroll
                for (int cb = 0; cb < 3; cb++) {
                    if (ca + cb > 2) continue;
#pragma unroll
                    for (int mt = 0; mt < 4; mt++)
#pragma unroll
                        for (int nt = 0; nt < 4; nt++)
                            mma16816(acc[mt][nt], aq[mt], &bq[cb][nt * 2]);
                }
            }
        }

        // ---- (3) store chunk c+1 into the other buffer (overlaps MMA drain) ----
        if (more) store_stage(cur ^ 1);

        // ---- (4) single barrier per chunk ----
        __syncthreads();
    }

    // ---- epilogue ----
    const int trow = lane >> 2;
    const int tcol = (lane & 3) * 2;
#pragma unroll
    for (int mt = 0; mt < 4; mt++) {
#pragma unroll
        for (int nt = 0; nt < 4; nt++) {
            const int row = m0 + wm + mt * 16 + trow;
            const int col = wn + nt * 8 + tcol;
            *reinterpret_cast<float2*>(Cout + (size_t)row * E + col) =
                make_float2(acc[mt][nt][0], acc[mt][nt][1]);
            *reinterpret_cast<float2*>(Cout + (size_t)(row + 8) * E + col) =
                make_float2(acc[mt][nt][2], acc[mt][nt][3]);
        }
    }
}

// ---------------- top-k: one warp per token, iterative exact argmax ----------------
__global__ __launch_bounds__(256) void topk_kernel(const float* __restrict__ C,
                                                   float* __restrict__ vals,
                                                   float* __restrict__ idxf) {
    const int token = (blockIdx.x * blockDim.x + threadIdx.x) >> 5;
    const int lane = threadIdx.x & 31;
    if (token >= T) return;

    // contiguous 4 experts per lane via one LDG.128 (tie->lowest-index preserved:
    // ids ascend within the lane scan, warp reduce breaks ties toward lower index)
    const float4 vv = *reinterpret_cast<const float4*>(C + (size_t)token * E + lane * 4);
    float v[4] = {vv.x, vv.y, vv.z, vv.w};
    int id[4] = {lane * 4, lane * 4 + 1, lane * 4 + 2, lane * 4 + 3};

    float topv[TOPK];
    int topi[TOPK];
#pragma unroll
    for (int it = 0; it < TOPK; it++) {
        float bv = v[0];
        int bi = id[0];
#pragma unroll
        for (int j = 1; j < 4; j++)
            if (v[j] > bv) { bv = v[j]; bi = id[j]; }
#pragma unroll
        for (int off = 16; off > 0; off >>= 1) {
            float ov = __shfl_xor_sync(0xFFFFFFFFu, bv, off);
            int oi = __shfl_xor_sync(0xFFFFFFFFu, bi, off);
            if (ov > bv || (ov == bv && oi < bi)) { bv = ov; bi = oi; }
        }
        topv[it] = bv;
        topi[it] = bi;
#pragma unroll
        for (int j = 0; j < 4; j++)
            if (id[j] == bi) v[j] = -INFINITY;
    }

    const float m = topv[0];
    float e[TOPK];
    float s = 0.0f;
#pragma unroll
    for (int i = 0; i < TOPK; i++) {
        e[i] = expf(topv[i] - m);
        s += e[i];
    }
    const float inv = 1.0f / s;

    if (lane < TOPK) {
        vals[(size_t)token * TOPK + lane] = e[lane] * inv;
        idxf[(size_t)token * TOPK + lane] = (float)topi[lane];
    }
}

extern "C" void kernel_launch(void* const* d_in, const int* in_sizes, int n_in,
                              void* d_out, int out_size) {
    const float* X = (const float*)d_in[0];  // [T, H]
    const float* W = (const float*)d_in[1];  // [E, H]
    float* out = (float*)d_out;
    float* logits = out;                      // T*E
    float* vals = out + (size_t)T * E;        // T*TOPK
    float* idxf = vals + (size_t)T * TOPK;    // T*TOPK

    cudaFuncSetAttribute(router_gemm_mma, cudaFuncAttributeMaxDynamicSharedMemorySize, SMEM_TOTAL);

    split_w_kernel<<<(E * H / 4) / 256, 256>>>(W);
    router_gemm_mma<<<T / BM, 256, SMEM_TOTAL>>>(X, logits);
    topk_kernel<<<T / 8, 256>>>(logits, vals, idxf);
}

// round 14
// speedup vs baseline: 1.4115x; 1.4115x over previous
#include <cuda_runtime.h>
#include <cuda_fp16.h>
#include <cstdint>
#include <math.h>

// ---------------- problem constants ----------------
constexpr int T = 16384;   // tokens
constexpr int H = 2048;    // hidden
constexpr int E = 128;     // experts
constexpr int TOPK = 8;

// ---------------- GEMM config ----------------
constexpr int BM = 128;               // tokens per CTA
constexpr int CHUNK = 32;             // fp32 k per pipeline chunk
constexpr int NCHUNK = H / CHUNK;     // 64
constexpr int TSTRIDE = 80;           // bytes per tile row: 64B data + 16B pad (conflict-free ldmatrix)
constexpr int TILE_B = 128 * TSTRIDE; // 10240 B per component tile
constexpr int STAGE_B = 4 * TILE_B;   // A1,A2,B1,B2 = 40960
constexpr int SMEM_TOTAL = 2 * STAGE_B;  // 81920

// W scale: 2^6 keeps fp16 split residuals out of subnormal range (W ~ N(0,0.02))
constexpr float WSCALE = 64.0f;
constexpr float INV_WSCALE = 1.0f / 64.0f;

// pre-split W components (fp16 2-way split of WSCALE * w), [E][H]
__device__ __align__(16) __half g_w1[E * H];
__device__ __align__(16) __half g_w2[E * H];

// ---------------- helpers ----------------
__device__ __forceinline__ uint32_t smem_u32(const void* p) {
    uint32_t a;
    asm("{ .reg .u64 t; cvta.to.shared.u64 t, %1; cvt.u32.u64 %0, t; }" : "=r"(a) : "l"(p));
    return a;
}
__device__ __forceinline__ void ldsm4(uint32_t* r, uint32_t addr) {
    asm volatile("ldmatrix.sync.aligned.m8n8.x4.shared.b16 {%0,%1,%2,%3}, [%4];"
                 : "=r"(r[0]), "=r"(r[1]), "=r"(r[2]), "=r"(r[3]) : "r"(addr));
}
__device__ __forceinline__ void mma16816(float* c, const uint32_t* a, const uint32_t* b) {
    asm volatile(
        "mma.sync.aligned.m16n8k16.row.col.f32.f16.f16.f32 "
        "{%0,%1,%2,%3}, {%4,%5,%6,%7}, {%8,%9}, {%0,%1,%2,%3};"
        : "+f"(c[0]), "+f"(c[1]), "+f"(c[2]), "+f"(c[3])
        : "r"(a[0]), "r"(a[1]), "r"(a[2]), "r"(a[3]), "r"(b[0]), "r"(b[1]));
}

// ---------------- W 2-way fp16 split precompute (scaled by WSCALE) ----------------
__global__ __launch_bounds__(256) void split_w_kernel(const float* __restrict__ W) {
    int i = blockIdx.x * blockDim.x + threadIdx.x;   // one float4 per thread
    float4 v = reinterpret_cast<const float4*>(W)[i];
    float s0 = v.x * WSCALE, s1 = v.y * WSCALE, s2 = v.z * WSCALE, s3 = v.w * WSCALE;
    __half2 a0 = __floats2half2_rn(s0, s1);
    __half2 a1 = __floats2half2_rn(s2, s3);
    float r0 = s0 - __low2float(a0), r1 = s1 - __high2float(a0);
    float r2 = s2 - __low2float(a1), r3 = s3 - __high2float(a1);
    __half2 b0 = __floats2half2_rn(r0, r1);
    __half2 b1 = __floats2half2_rn(r2, r3);
    reinterpret_cast<__half2*>(g_w1)[2 * i] = a0;
    reinterpret_cast<__half2*>(g_w1)[2 * i + 1] = a1;
    reinterpret_cast<__half2*>(g_w2)[2 * i] = b0;
    reinterpret_cast<__half2*>(g_w2)[2 * i + 1] = b1;
}

// ---------------- fp16x3 HMMA router GEMM ----------------
// C[t][e] = X[t][:] . W[e][:]; 2-way fp16 splits, terms h1g1+h1g2+h2g1.
// Per-product error ~2^-22 — below fp32 accumulation noise.
__global__ __launch_bounds__(256, 1) void router_gemm_mma(const float* __restrict__ X,
                                                          float* __restrict__ Cout) {
    extern __shared__ char smem[];
    const int tid = threadIdx.x;
    const int wid = tid >> 5;
    const int lane = tid & 31;
    const int m0 = blockIdx.x * BM;

    // gmem load mapping: 2 threads per row, 16 elems (64B fp32 / 32B fp16) each
    const int lrow = tid >> 1;          // 0..127
    const int lhalf = tid & 1;          // 0/1
    const float* Xbase = X + (size_t)(m0 + lrow) * H + lhalf * 16;
    const __half* Wb1 = g_w1 + (size_t)lrow * H + lhalf * 16;
    const __half* Wb2 = g_w2 + (size_t)lrow * H + lhalf * 16;
    const uint32_t rb = (uint32_t)lrow * TSTRIDE + lhalf * 32;  // smem tile byte base

    // warp tile: 2 warps in M (64 rows), 4 warps in N (32 cols)
    const int wm = (wid >> 2) * 64;
    const int wn = (wid & 3) * 32;

    float acc[4][4][4];
#pragma unroll
    for (int mt = 0; mt < 4; mt++)
#pragma unroll
        for (int nt = 0; nt < 4; nt++)
#pragma unroll
            for (int j = 0; j < 4; j++) acc[mt][nt][j] = 0.0f;

    float4 xv[4];
    uint4 wv[2][2];   // [component][16B half] — 32 bytes per component per thread

    const uint32_t sbase = smem_u32(smem);

    // store regs -> stage buffer `buf` (split X into 2 fp16 comps; copy W comps)
    auto store_stage = [&](int buf) {
        char* stage = smem + buf * STAGE_B;
        char* A1 = stage;
        char* A2 = stage + TILE_B;
#pragma unroll
        for (int q = 0; q < 4; q++) {
            float4 v = xv[q];
            uint32_t off = rb + q * 8;
            __half2 p1a = __floats2half2_rn(v.x, v.y);
            __half2 p1b = __floats2half2_rn(v.z, v.w);
            *reinterpret_cast<uint2*>(A1 + off) =
                make_uint2(*reinterpret_cast<uint32_t*>(&p1a), *reinterpret_cast<uint32_t*>(&p1b));
            float r0 = v.x - __low2float(p1a);
            float r1 = v.y - __high2float(p1a);
            float r2 = v.z - __low2float(p1b);
            float r3 = v.w - __high2float(p1b);
            __half2 p2a = __floats2half2_rn(r0, r1);
            __half2 p2b = __floats2half2_rn(r2, r3);
            *reinterpret_cast<uint2*>(A2 + off) =
                make_uint2(*reinterpret_cast<uint32_t*>(&p2a), *reinterpret_cast<uint32_t*>(&p2b));
        }
#pragma unroll
        for (int comp = 0; comp < 2; comp++) {
            char* Bt = stage + (2 + comp) * TILE_B;
            *reinterpret_cast<uint4*>(Bt + rb) = wv[comp][0];
            *reinterpret_cast<uint4*>(Bt + rb + 16) = wv[comp][1];
        }
    };

    // prologue: load + stage chunk 0 into buffer 0
    {
#pragma unroll
        for (int q = 0; q < 4; q++) xv[q] = *reinterpret_cast<const float4*>(Xbase + q * 4);
        wv[0][0] = *reinterpret_cast<const uint4*>(Wb1);
        wv[0][1] = *reinterpret_cast<const uint4*>(Wb1 + 8);
        wv[1][0] = *reinterpret_cast<const uint4*>(Wb2);
        wv[1][1] = *reinterpret_cast<const uint4*>(Wb2 + 8);
        store_stage(0);
    }
    __syncthreads();

#pragma unroll 1
    for (int c = 0; c < NCHUNK; c++) {
        const int cur = c & 1;
        const bool more = (c + 1 < NCHUNK);

        // ---- (1) prefetch LDGs for chunk c+1 ----
        if (more) {
            const float* xp = Xbase + (c + 1) * CHUNK;
#pragma unroll
            for (int q = 0; q < 4; q++) xv[q] = *reinterpret_cast<const float4*>(xp + q * 4);
            const int wo = (c + 1) * CHUNK;
            wv[0][0] = *reinterpret_cast<const uint4*>(Wb1 + wo);
            wv[0][1] = *reinterpret_cast<const uint4*>(Wb1 + wo + 8);
            wv[1][0] = *reinterpret_cast<const uint4*>(Wb2 + wo);
            wv[1][1] = *reinterpret_cast<const uint4*>(Wb2 + wo + 8);
        }

        // ---- (2) compute on stage cur ----
        const uint32_t st = sbase + cur * STAGE_B;
#pragma unroll
        for (int ks = 0; ks < 2; ks++) {
            // B fragments: 2 comps x 4 n-tiles
            uint32_t bq[2][8];
            {
                const uint32_t nrow = wn + (lane & 7) + ((lane >> 4) & 1) * 8;
                const uint32_t koff = ks * 32 + ((lane >> 3) & 1) * 16;
#pragma unroll
                for (int comp = 0; comp < 2; comp++) {
                    uint32_t basea = st + (2 + comp) * TILE_B + nrow * TSTRIDE + koff;
                    ldsm4(&bq[comp][0], basea);                  // n-tiles 0,1
                    ldsm4(&bq[comp][4], basea + 16 * TSTRIDE);   // n-tiles 2,3
                }
            }
            // A comps; terms: (h1,g1), (h1,g2), (h2,g1)
            const uint32_t arow = wm + (lane & 15);
            const uint32_t akoff = ks * 32 + (lane >> 4) * 16;
#pragma unroll
            for (int ca = 0; ca < 2; ca++) {
                uint32_t abase = st + ca * TILE_B + arow * TSTRIDE + akoff;
                uint32_t aq[4][4];
#pragma unroll
                for (int mt = 0; mt < 4; mt++) ldsm4(aq[mt], abase + mt * 16 * TSTRIDE);
#pragma unroll
                for (int cb = 0; cb < 2; cb++) {
                    if (ca + cb > 1) continue;   // 3 terms
#pragma unroll
                    for (int mt = 0; mt < 4; mt++)
#pragma unroll
                        for (int nt = 0; nt < 4; nt++)
                            mma16816(acc[mt][nt], aq[mt], &bq[cb][nt * 2]);
                }
            }
        }

        // ---- (3) store chunk c+1 into the other buffer ----
        if (more) store_stage(cur ^ 1);

        // ---- (4) single barrier per chunk ----
        __syncthreads();
    }

    // ---- epilogue: unscale (exact power of 2) and write ----
    const int trow = lane >> 2;
    const int tcol = (lane & 3) * 2;
#pragma unroll
    for (int mt = 0; mt < 4; mt++) {
#pragma unroll
        for (int nt = 0; nt < 4; nt++) {
            const int row = m0 + wm + mt * 16 + trow;
            const int col = wn + nt * 8 + tcol;
            *reinterpret_cast<float2*>(Cout + (size_t)row * E + col) =
                make_float2(acc[mt][nt][0] * INV_WSCALE, acc[mt][nt][1] * INV_WSCALE);
            *reinterpret_cast<float2*>(Cout + (size_t)(row + 8) * E + col) =
                make_float2(acc[mt][nt][2] * INV_WSCALE, acc[mt][nt][3] * INV_WSCALE);
        }
    }
}

// ---------------- top-k: one warp per token, iterative exact argmax ----------------
__global__ __launch_bounds__(256) void topk_kernel(const float* __restrict__ C,
                                                   float* __restrict__ vals,
                                                   float* __restrict__ idxf) {
    const int token = (blockIdx.x * blockDim.x + threadIdx.x) >> 5;
    const int lane = threadIdx.x & 31;
    if (token >= T) return;

    const float4 vv = *reinterpret_cast<const float4*>(C + (size_t)token * E + lane * 4);
    float v[4] = {vv.x, vv.y, vv.z, vv.w};
    int id[4] = {lane * 4, lane * 4 + 1, lane * 4 + 2, lane * 4 + 3};

    float topv[TOPK];
    int topi[TOPK];
#pragma unroll
    for (int it = 0; it < TOPK; it++) {
        float bv = v[0];
        int bi = id[0];
#pragma unroll
        for (int j = 1; j < 4; j++)
            if (v[j] > bv) { bv = v[j]; bi = id[j]; }
#pragma unroll
        for (int off = 16; off > 0; off >>= 1) {
            float ov = __shfl_xor_sync(0xFFFFFFFFu, bv, off);
            int oi = __shfl_xor_sync(0xFFFFFFFFu, bi, off);
            if (ov > bv || (ov == bv && oi < bi)) { bv = ov; bi = oi; }
        }
        topv[it] = bv;
        topi[it] = bi;
#pragma unroll
        for (int j = 0; j < 4; j++)
            if (id[j] == bi) v[j] = -INFINITY;
    }

    const float m = topv[0];
    float e[TOPK];
    float s = 0.0f;
#pragma unroll
    for (int i = 0; i < TOPK; i++) {
        e[i] = expf(topv[i] - m);
        s += e[i];
    }
    const float inv = 1.0f / s;

    if (lane < TOPK) {
        vals[(size_t)token * TOPK + lane] = e[lane] * inv;
        idxf[(size_t)token * TOPK + lane] = (float)topi[lane];
    }
}

extern "C" void kernel_launch(void* const* d_in, const int* in_sizes, int n_in,
                              void* d_out, int out_size) {
    const float* X = (const float*)d_in[0];  // [T, H]
    const float* W = (const float*)d_in[1];  // [E, H]
    float* out = (float*)d_out;
    float* logits = out;                      // T*E
    float* vals = out + (size_t)T * E;        // T*TOPK
    float* idxf = vals + (size_t)T * TOPK;    // T*TOPK

    cudaFuncSetAttribute(router_gemm_mma, cudaFuncAttributeMaxDynamicSharedMemorySize, SMEM_TOTAL);

    split_w_kernel<<<(E * H / 4) / 256, 256>>>(W);
    router_gemm_mma<<<T / BM, 256, SMEM_TOTAL>>>(X, logits);
    topk_kernel<<<T / 8, 256>>>(logits, vals, idxf);
}

// round 15
// speedup vs baseline: 1.4636x; 1.0369x over previous
#include <cuda_runtime.h>
#include <cuda_fp16.h>
#include <cstdint>
#include <math.h>

// ---------------- problem constants ----------------
constexpr int T = 16384;   // tokens
constexpr int H = 2048;    // hidden
constexpr int E = 128;     // experts
constexpr int TOPK = 8;

// ---------------- GEMM config ----------------
constexpr int BM = 128;               // tokens per CTA
constexpr int CHUNK = 32;             // fp32 k per pipeline chunk
constexpr int NCHUNK = H / CHUNK;     // 64
constexpr int TSTRIDE = 80;           // bytes per tile row: 64B data + 16B pad (conflict-free ldmatrix)
constexpr int TILE_B = 128 * TSTRIDE; // 10240 B per component tile
constexpr int STAGE_B = 4 * TILE_B;   // A1,A2,B1,B2 = 40960
constexpr int SMEM_TOTAL = 2 * STAGE_B;  // 81920

// W scale: 2^6 keeps fp16 split residuals out of subnormal range (W ~ N(0,0.02))
constexpr float WSCALE = 64.0f;
constexpr float INV_WSCALE = 1.0f / 64.0f;

// ---------------- helpers ----------------
__device__ __forceinline__ uint32_t smem_u32(const void* p) {
    uint32_t a;
    asm("{ .reg .u64 t; cvta.to.shared.u64 t, %1; cvt.u32.u64 %0, t; }" : "=r"(a) : "l"(p));
    return a;
}
__device__ __forceinline__ void ldsm4(uint32_t* r, uint32_t addr) {
    asm volatile("ldmatrix.sync.aligned.m8n8.x4.shared.b16 {%0,%1,%2,%3}, [%4];"
                 : "=r"(r[0]), "=r"(r[1]), "=r"(r[2]), "=r"(r[3]) : "r"(addr));
}
__device__ __forceinline__ void mma16816(float* c, const uint32_t* a, const uint32_t* b) {
    asm volatile(
        "mma.sync.aligned.m16n8k16.row.col.f32.f16.f16.f32 "
        "{%0,%1,%2,%3}, {%4,%5,%6,%7}, {%8,%9}, {%0,%1,%2,%3};"
        : "+f"(c[0]), "+f"(c[1]), "+f"(c[2]), "+f"(c[3])
        : "r"(a[0]), "r"(a[1]), "r"(a[2]), "r"(a[3]), "r"(b[0]), "r"(b[1]));
}

// order-preserving float->u32 bijection (and exact inverse)
__device__ __forceinline__ uint32_t f2mono(float f) {
    uint32_t b = __float_as_uint(f);
    return b ^ ((uint32_t)((int32_t)b >> 31) | 0x80000000u);
}
__device__ __forceinline__ float mono2f(uint32_t u) {
    uint32_t b = u ^ ((uint32_t)((int32_t)(~u) >> 31) | 0x80000000u);
    return __uint_as_float(b);
}

// ---------------- fp16x3 HMMA router GEMM, W split fused ----------------
// C[t][e] = X[t][:] . W[e][:]; 2-way fp16 splits of both operands,
// terms h1g1+h1g2+h2g1 (dropped h2g2 ~2^-24). fp32-equivalent in practice.
__global__ __launch_bounds__(256, 1) void router_gemm_mma(const float* __restrict__ X,
                                                          const float* __restrict__ W,
                                                          float* __restrict__ Cout) {
    extern __shared__ char smem[];
    const int tid = threadIdx.x;
    const int wid = tid >> 5;
    const int lane = tid & 31;
    const int m0 = blockIdx.x * BM;

    // gmem load mapping: 2 threads per row, 16 fp32 (64B) each
    const int lrow = tid >> 1;          // 0..127
    const int lhalf = tid & 1;          // 0/1
    const float* Xbase = X + (size_t)(m0 + lrow) * H + lhalf * 16;
    const float* Wbase = W + (size_t)lrow * H + lhalf * 16;
    const uint32_t rb = (uint32_t)lrow * TSTRIDE + lhalf * 32;  // smem tile byte base

    // warp tile: 2 warps in M (64 rows), 4 warps in N (32 cols)
    const int wm = (wid >> 2) * 64;
    const int wn = (wid & 3) * 32;

    float acc[4][4][4];
#pragma unroll
    for (int mt = 0; mt < 4; mt++)
#pragma unroll
        for (int nt = 0; nt < 4; nt++)
#pragma unroll
            for (int j = 0; j < 4; j++) acc[mt][nt][j] = 0.0f;

    float4 xv[4];
    float4 wfv[4];

    const uint32_t sbase = smem_u32(smem);

    // split a float4 (already scaled if needed) into two fp16 pairs and store
    auto split_store = [](char* C1, char* C2, uint32_t off, float4 v) {
        __half2 p1a = __floats2half2_rn(v.x, v.y);
        __half2 p1b = __floats2half2_rn(v.z, v.w);
        *reinterpret_cast<uint2*>(C1 + off) =
            make_uint2(*reinterpret_cast<uint32_t*>(&p1a), *reinterpret_cast<uint32_t*>(&p1b));
        float r0 = v.x - __low2float(p1a);
        float r1 = v.y - __high2float(p1a);
        float r2 = v.z - __low2float(p1b);
        float r3 = v.w - __high2float(p1b);
        __half2 p2a = __floats2half2_rn(r0, r1);
        __half2 p2b = __floats2half2_rn(r2, r3);
        *reinterpret_cast<uint2*>(C2 + off) =
            make_uint2(*reinterpret_cast<uint32_t*>(&p2a), *reinterpret_cast<uint32_t*>(&p2b));
    };

    // stage buffer `buf`: split X regs -> A1,A2; split scaled-W regs -> B1,B2
    auto store_stage = [&](int buf) {
        char* stage = smem + buf * STAGE_B;
        char* A1 = stage;
        char* A2 = stage + TILE_B;
        char* B1 = stage + 2 * TILE_B;
        char* B2 = stage + 3 * TILE_B;
#pragma unroll
        for (int q = 0; q < 4; q++) {
            uint32_t off = rb + q * 8;
            split_store(A1, A2, off, xv[q]);
            float4 w = wfv[q];
            w.x *= WSCALE; w.y *= WSCALE; w.z *= WSCALE; w.w *= WSCALE;  // exact (2^6)
            split_store(B1, B2, off, w);
        }
    };

    // prologue: load + stage chunk 0 into buffer 0
    {
#pragma unroll
        for (int q = 0; q < 4; q++) {
            xv[q] = *reinterpret_cast<const float4*>(Xbase + q * 4);
            wfv[q] = *reinterpret_cast<const float4*>(Wbase + q * 4);
        }
        store_stage(0);
    }
    __syncthreads();

#pragma unroll 1
    for (int c = 0; c < NCHUNK; c++) {
        const int cur = c & 1;
        const bool more = (c + 1 < NCHUNK);

        // ---- (1) prefetch LDGs for chunk c+1 ----
        if (more) {
            const float* xp = Xbase + (c + 1) * CHUNK;
            const float* wp = Wbase + (c + 1) * CHUNK;
#pragma unroll
            for (int q = 0; q < 4; q++) {
                xv[q] = *reinterpret_cast<const float4*>(xp + q * 4);
                wfv[q] = *reinterpret_cast<const float4*>(wp + q * 4);
            }
        }

        // ---- (2) compute on stage cur ----
        const uint32_t st = sbase + cur * STAGE_B;
#pragma unroll
        for (int ks = 0; ks < 2; ks++) {
            // B fragments: 2 comps x 4 n-tiles
            uint32_t bq[2][8];
            {
                const uint32_t nrow = wn + (lane & 7) + ((lane >> 4) & 1) * 8;
                const uint32_t koff = ks * 32 + ((lane >> 3) & 1) * 16;
#pragma unroll
                for (int comp = 0; comp < 2; comp++) {
                    uint32_t basea = st + (2 + comp) * TILE_B + nrow * TSTRIDE + koff;
                    ldsm4(&bq[comp][0], basea);                  // n-tiles 0,1
                    ldsm4(&bq[comp][4], basea + 16 * TSTRIDE);   // n-tiles 2,3
                }
            }
            // A comps; terms: (h1,g1), (h1,g2), (h2,g1)
            const uint32_t arow = wm + (lane & 15);
            const uint32_t akoff = ks * 32 + (lane >> 4) * 16;
#pragma unroll
            for (int ca = 0; ca < 2; ca++) {
                uint32_t abase = st + ca * TILE_B + arow * TSTRIDE + akoff;
                uint32_t aq[4][4];
#pragma unroll
                for (int mt = 0; mt < 4; mt++) ldsm4(aq[mt], abase + mt * 16 * TSTRIDE);
#pragma unroll
                for (int cb = 0; cb < 2; cb++) {
                    if (ca + cb > 1) continue;   // 3 terms
#pragma unroll
                    for (int mt = 0; mt < 4; mt++)
#pragma unroll
                        for (int nt = 0; nt < 4; nt++)
                            mma16816(acc[mt][nt], aq[mt], &bq[cb][nt * 2]);
                }
            }
        }

        // ---- (3) store chunk c+1 into the other buffer ----
        if (more) store_stage(cur ^ 1);

        // ---- (4) single barrier per chunk ----
        __syncthreads();
    }

    // ---- epilogue: unscale (exact power of 2) and write ----
    const int trow = lane >> 2;
    const int tcol = (lane & 3) * 2;
#pragma unroll
    for (int mt = 0; mt < 4; mt++) {
#pragma unroll
        for (int nt = 0; nt < 4; nt++) {
            const int row = m0 + wm + mt * 16 + trow;
            const int col = wn + nt * 8 + tcol;
            *reinterpret_cast<float2*>(Cout + (size_t)row * E + col) =
                make_float2(acc[mt][nt][0] * INV_WSCALE, acc[mt][nt][1] * INV_WSCALE);
            *reinterpret_cast<float2*>(Cout + (size_t)(row + 8) * E + col) =
                make_float2(acc[mt][nt][2] * INV_WSCALE, acc[mt][nt][3] * INV_WSCALE);
        }
    }
}

// ---------------- top-k: monotone-u32 keys + redux.sync ----------------
// One warp per token. Keys preserve exact float order; ties -> equal keys ->
// redux.min over indices = lowest index, matching jax.lax.top_k. Values are
// recovered exactly via the inverse bijection.
__global__ __launch_bounds__(256) void topk_kernel(const float* __restrict__ C,
                                                   float* __restrict__ vals,
                                                   float* __restrict__ idxf) {
    const int token = (blockIdx.x * blockDim.x + threadIdx.x) >> 5;
    const int lane = threadIdx.x & 31;

    const float4 vv = *reinterpret_cast<const float4*>(C + (size_t)token * E + lane * 4);
    uint32_t k[4] = {f2mono(vv.x), f2mono(vv.y), f2mono(vv.z), f2mono(vv.w)};
    const uint32_t id0 = lane * 4;

    uint32_t topm[TOPK], topi[TOPK];
#pragma unroll
    for (int it = 0; it < TOPK; it++) {
        uint32_t lm = max(max(k[0], k[1]), max(k[2], k[3]));
        uint32_t m;
        asm("redux.sync.max.u32 %0, %1, 0xffffffff;" : "=r"(m) : "r"(lm));
        uint32_t cand = 0xFFu;
#pragma unroll
        for (int j = 0; j < 4; j++) cand = min(cand, (k[j] == m) ? (id0 + j) : 0xFFu);
        uint32_t widx;
        asm("redux.sync.min.u32 %0, %1, 0xffffffff;" : "=r"(widx) : "r"(cand));
        topm[it] = m;
        topi[it] = widx;
#pragma unroll
        for (int j = 0; j < 4; j++)
            if (id0 + j == widx) k[j] = 0u;   // retire (0 < any finite key)
    }

    // normalized weights: exp(l_i - m) / sum_top8 exp(l_j - m)
    float tv[TOPK];
#pragma unroll
    for (int i = 0; i < TOPK; i++) tv[i] = mono2f(topm[i]);
    const float mx = tv[0];
    float e[TOPK];
    float s = 0.0f;
#pragma unroll
    for (int i = 0; i < TOPK; i++) {
        e[i] = expf(tv[i] - mx);
        s += e[i];
    }
    const float inv = 1.0f / s;

    if (lane < TOPK) {
        vals[(size_t)token * TOPK + lane] = e[lane] * inv;
        idxf[(size_t)token * TOPK + lane] = (float)topi[lane];
    }
}

extern "C" void kernel_launch(void* const* d_in, const int* in_sizes, int n_in,
                              void* d_out, int out_size) {
    const float* X = (const float*)d_in[0];  // [T, H]
    const float* W = (const float*)d_in[1];  // [E, H]
    float* out = (float*)d_out;
    float* logits = out;                      // T*E
    float* vals = out + (size_t)T * E;        // T*TOPK
    float* idxf = vals + (size_t)T * TOPK;    // T*TOPK

    cudaFuncSetAttribute(router_gemm_mma, cudaFuncAttributeMaxDynamicSharedMemorySize, SMEM_TOTAL);

    router_gemm_mma<<<T / BM, 256, SMEM_TOTAL>>>(X, W, logits);
    topk_kernel<<<T / 8, 256>>>(logits, vals, idxf);
}